// round 10
// baseline (speedup 1.0000x reference)
#include <cuda_runtime.h>
#include <cstdint>

// Problem constants (B=4, L=4096, C=1024, K=4096)
#define NPTS 16384
#define CDIM 1024
#define KCB  4096

// Device scratch (no allocations allowed)
__device__ float              g_feat[NPTS * CDIM];   // normalized points (64 MB)
__device__ float              g_cbn2[KCB];           // ||cb_k||^2
__device__ float              g_sums[KCB * CDIM];    // per-cluster sums (16 MB)
__device__ int                g_cnt[KCB];            // per-cluster counts
__device__ unsigned long long g_best[NPTS];          // packed (orderable_f32 << 32) | idx

// Packed fp32x2 FMA (sm_103a FFMA2; two independent IEEE fp32 FMAs)
#define FFMA2(d, a, b, c) \
    asm("fma.rn.f32x2 %0, %1, %2, %3;" : "=l"(d) : "l"(a), "l"(b), "l"(c))

// ---------------------------------------------------------------------------
// Init: zero accumulators, set best to +inf (graph-replay safe)
// ---------------------------------------------------------------------------
__global__ void init_kernel() {
    int i = blockIdx.x * blockDim.x + threadIdx.x;
    int stride = gridDim.x * blockDim.x;
    for (int j = i; j < KCB * CDIM; j += stride) g_sums[j] = 0.f;
    for (int j = i; j < KCB; j += stride) g_cnt[j] = 0;
    for (int j = i; j < NPTS; j += stride) g_best[j] = 0xFFFFFFFFFFFFFFFFull;
}

// ---------------------------------------------------------------------------
// Row-normalize hidden_states -> g_feat   (one 256-thread block per row)
// ---------------------------------------------------------------------------
__global__ void norm_feat_kernel(const float* __restrict__ hs) {
    int row = blockIdx.x;
    int t = threadIdx.x;
    float v[4];
    float ss = 0.f;
#pragma unroll
    for (int j = 0; j < 4; j++) {
        v[j] = hs[(size_t)row * CDIM + t + j * 256];
        ss += v[j] * v[j];
    }
    __shared__ float red[256];
    red[t] = ss;
    __syncthreads();
    for (int s = 128; s > 0; s >>= 1) {
        if (t < s) red[t] += red[t + s];
        __syncthreads();
    }
    float inv = 1.f / fmaxf(sqrtf(red[0]), 1e-6f);
#pragma unroll
    for (int j = 0; j < 4; j++)
        g_feat[(size_t)row * CDIM + t + j * 256] = v[j] * inv;
}

// ---------------------------------------------------------------------------
// ||cb_k||^2  (one block per code)
// ---------------------------------------------------------------------------
__global__ void cbn2_kernel(const float* __restrict__ cb) {
    int row = blockIdx.x;
    int t = threadIdx.x;
    float ss = 0.f;
#pragma unroll
    for (int j = 0; j < 4; j++) {
        float x = cb[(size_t)row * CDIM + t + j * 256];
        ss += x * x;
    }
    __shared__ float red[256];
    red[t] = ss;
    __syncthreads();
    for (int s = 128; s > 0; s >>= 1) {
        if (t < s) red[t] += red[t + s];
        __syncthreads();
    }
    if (t == 0) g_cbn2[row] = red[0];
}

// ---------------------------------------------------------------------------
// Fused GEMM + argmin with packed f32x2 FMAs, conflict-free smem, and
// register-level software pipelining of the global tile loads.
//
// 256 threads; block tile 256 rows x 128 codes (ONE code tile per block);
// C-chunks of 16. Thread tile: 16 rows (8 packed pairs, pair = tx + 16p) x
// 8 codes (k = ty + 16s), tx = t&15, ty = t>>4.
//  - As[c][256] transposed rows: LDS.64 at [2*(tx+16p)]; 16 lanes cover 128
//    contiguous bytes (all 32 banks once) + upper-half broadcast -> 1 wf.
//  - Bs[c][256] duplicated codes ([2k],[2k+1]): depends only on ty ->
//    half-warp broadcast -> 1 wf.
//  - SSTRIDE = 258: 4*258 == 8 (mod 32) -> the four c-rows of one thread's
//    STS land in banks {0,8,16,24} -> conflict-free stores.
//  - Pipeline: per chunk {sync; STS prefetched regs; sync; LDG next chunk;
//    compute} so L2 latency overlaps the compute phase.
//  - Chunk loop pinned "#pragma unroll 1": cc-loop body ~20 KB SASS (fits
//    I$ L1.5); outer unrolling would thrash I$.
//  - ONE code tile per block keeps bestv/besti OUT of the mainloop live set
//    (~211 regs live in mainloop).
//  - __launch_bounds__(256, 1): explicitly 1 CTA/SM so ptxas allocates up to
//    255 regs instead of heuristically capping at 128 and spilling the
//    128-reg accumulator file.
//  - Grid (64, 32) = 2048 blocks = 13.84 waves on 148 SMs -> 98.8% SM-time
//    utilization.
// Merges via atomicMin on packed (orderable_key<<32)|idx so ties pick the
// smallest index (jnp.argmin semantics).
// ---------------------------------------------------------------------------
#define BM 256
#define BKC 128                  // codes per tile (= per block)
#define BC 16                    // c-chunk
#define SSTRIDE 258              // floats per smem row (bank analysis above)
#define NCHUNK (CDIM / BC)       // 64

__global__ __launch_bounds__(256, 1) void argmin_kernel(const float* __restrict__ cb) {
    __shared__ __align__(16) float As[BC][SSTRIDE];
    __shared__ __align__(16) float Bs[BC][SSTRIDE];

    int t = threadIdx.x;
    int tx = t & 15;
    int ty = t >> 4;
    int rowBase = blockIdx.x * BM;
    int kBase = blockIdx.y * BKC;

    // Per-thread load coordinates (fixed across chunks)
    int ra[4], ca[4];            // A: 4 float4 per thread
#pragma unroll
    for (int i = 0; i < 4; i++) {
        int q = t + i * 256;     // 0..1023
        ra[i] = q >> 2;          // row 0..255
        ca[i] = (q & 3) * 4;     // 0,4,8,12
    }
    int rb[2], cbc[2];           // B: 2 float4 per thread
#pragma unroll
    for (int i = 0; i < 2; i++) {
        int q = t + i * 256;     // 0..511
        rb[i] = q >> 2;          // code 0..127
        cbc[i] = (q & 3) * 4;
    }

    float4 fa[4], fb[2];
    // Prefetch chunk 0
#pragma unroll
    for (int i = 0; i < 4; i++)
        fa[i] = *(const float4*)&g_feat[(size_t)(rowBase + ra[i]) * CDIM + ca[i]];
#pragma unroll
    for (int i = 0; i < 2; i++)
        fb[i] = *(const float4*)&cb[(size_t)(kBase + rb[i]) * CDIM + cbc[i]];

    unsigned long long acc[8][8];  // [row-pair p][code s], packed f32x2
#pragma unroll
    for (int p = 0; p < 8; p++)
#pragma unroll
        for (int s = 0; s < 8; s++) acc[p][s] = 0ull;

#pragma unroll 1
    for (int ch = 0; ch < NCHUNK; ++ch) {
        __syncthreads();  // previous compute done reading smem
        // Store prefetched tiles (conflict-free per SSTRIDE analysis)
#pragma unroll
        for (int i = 0; i < 4; i++) {
            As[ca[i] + 0][ra[i]] = fa[i].x; As[ca[i] + 1][ra[i]] = fa[i].y;
            As[ca[i] + 2][ra[i]] = fa[i].z; As[ca[i] + 3][ra[i]] = fa[i].w;
        }
#pragma unroll
        for (int i = 0; i < 2; i++) {
            *(float2*)&Bs[cbc[i] + 0][2 * rb[i]] = make_float2(fb[i].x, fb[i].x);
            *(float2*)&Bs[cbc[i] + 1][2 * rb[i]] = make_float2(fb[i].y, fb[i].y);
            *(float2*)&Bs[cbc[i] + 2][2 * rb[i]] = make_float2(fb[i].z, fb[i].z);
            *(float2*)&Bs[cbc[i] + 3][2 * rb[i]] = make_float2(fb[i].w, fb[i].w);
        }
        __syncthreads();

        // Prefetch next chunk while computing this one
        if (ch + 1 < NCHUNK) {
            int nc0 = (ch + 1) * BC;
#pragma unroll
            for (int i = 0; i < 4; i++)
                fa[i] = *(const float4*)&g_feat[(size_t)(rowBase + ra[i]) * CDIM + nc0 + ca[i]];
#pragma unroll
            for (int i = 0; i < 2; i++)
                fb[i] = *(const float4*)&cb[(size_t)(kBase + rb[i]) * CDIM + nc0 + cbc[i]];
        }

#pragma unroll
        for (int cc = 0; cc < BC; ++cc) {
            unsigned long long a[8], b[8];
#pragma unroll
            for (int p = 0; p < 8; p++)
                a[p] = *(const unsigned long long*)&As[cc][2 * (tx + 16 * p)];
#pragma unroll
            for (int s = 0; s < 8; s++)
                b[s] = *(const unsigned long long*)&Bs[cc][2 * (ty + 16 * s)];
#pragma unroll
            for (int p = 0; p < 8; p++)
#pragma unroll
                for (int s = 0; s < 8; s++)
                    FFMA2(acc[p][s], a[p], b[s], acc[p][s]);
        }
    }

    // Epilogue: best arrays are born here (after acc's last full use) so they
    // never contend with the mainloop register budget.
    float bestv[16];
    int besti[16];
#pragma unroll
    for (int i = 0; i < 16; i++) { bestv[i] = 3.4e38f; besti[i] = 0x7fffffff; }

    // score = ||cb||^2 - 2*dot ; strict < keeps smallest index (k ascends
    // with s for each thread).
#pragma unroll
    for (int s = 0; s < 8; s++) {
        int k = kBase + ty + 16 * s;
        float c2 = g_cbn2[k];
#pragma unroll
        for (int p = 0; p < 8; p++) {
            float dlo = __uint_as_float((unsigned)(acc[p][s] & 0xFFFFFFFFull));
            float dhi = __uint_as_float((unsigned)(acc[p][s] >> 32));
            float slo = fmaf(-2.f, dlo, c2);
            float shi = fmaf(-2.f, dhi, c2);
            if (slo < bestv[2 * p])     { bestv[2 * p] = slo;     besti[2 * p] = k; }
            if (shi < bestv[2 * p + 1]) { bestv[2 * p + 1] = shi; besti[2 * p + 1] = k; }
        }
    }

    // Lanes l and l^16 hold the same rows (same tx; ty differs by 1) ->
    // intra-warp merge over their two code subsets, then the lower half-warp
    // commits with atomicMin (cross-warp/cross-block merge).
#pragma unroll
    for (int i = 0; i < 16; i++) {
        float v = bestv[i];
        int idx = besti[i];
        float ov = __shfl_xor_sync(0xFFFFFFFFu, v, 16);
        int oi = __shfl_xor_sync(0xFFFFFFFFu, idx, 16);
        if (ov < v || (ov == v && oi < idx)) { v = ov; idx = oi; }
        if ((t & 16) == 0) {
            int p = i >> 1;
            int row = rowBase + 2 * (tx + 16 * p) + (i & 1);
            unsigned key = __float_as_uint(v);
            key = (key & 0x80000000u) ? ~key : (key | 0x80000000u);
            unsigned long long packed =
                ((unsigned long long)key << 32) | (unsigned)idx;
            atomicMin(&g_best[row], packed);
        }
    }
}

// ---------------------------------------------------------------------------
// Decode ids, write them out, and scatter-add feat rows into cluster sums.
// ---------------------------------------------------------------------------
__global__ void scatter_kernel(float* __restrict__ out_ids) {
    int row = blockIdx.x;
    __shared__ int sidx;
    if (threadIdx.x == 0) {
        int idx = (int)(g_best[row] & 0xFFFFFFFFull);
        sidx = idx;
        out_ids[row] = (float)idx;
        atomicAdd(&g_cnt[idx], 1);
    }
    __syncthreads();
    int idx = sidx;
    const float* f = &g_feat[(size_t)row * CDIM];
    float* s = &g_sums[(size_t)idx * CDIM];
#pragma unroll
    for (int j = 0; j < 4; j++) {
        int c = threadIdx.x + j * 256;
        atomicAdd(&s[c], f[c]);
    }
}

// ---------------------------------------------------------------------------
// EMA update: mean = normalize(sums / max(cnt,1));
// new = normalize(0.99*cb + 0.01*mean); keep old code if cnt == 0.
// ---------------------------------------------------------------------------
__global__ void update_kernel(const float* __restrict__ cb, float* __restrict__ out_cb) {
    int k = blockIdx.x;
    int t = threadIdx.x;
    int cnt = g_cnt[k];
    float denom = fmaxf((float)cnt, 1.f);

    float m[4], c[4];
    float ss = 0.f;
#pragma unroll
    for (int j = 0; j < 4; j++) {
        int col = t + j * 256;
        m[j] = g_sums[(size_t)k * CDIM + col] / denom;
        c[j] = cb[(size_t)k * CDIM + col];
        ss += m[j] * m[j];
    }
    __shared__ float red[256];
    red[t] = ss;
    __syncthreads();
    for (int s = 128; s > 0; s >>= 1) {
        if (t < s) red[t] += red[t + s];
        __syncthreads();
    }
    float inv1 = 1.f / fmaxf(sqrtf(red[0]), 1e-6f);

    float v[4];
    float ss2 = 0.f;
#pragma unroll
    for (int j = 0; j < 4; j++) {
        v[j] = 0.99f * c[j] + 0.01f * (m[j] * inv1);
        ss2 += v[j] * v[j];
    }
    __syncthreads();
    red[t] = ss2;
    __syncthreads();
    for (int s = 128; s > 0; s >>= 1) {
        if (t < s) red[t] += red[t + s];
        __syncthreads();
    }
    float inv2 = 1.f / fmaxf(sqrtf(red[0]), 1e-6f);

#pragma unroll
    for (int j = 0; j < 4; j++) {
        int col = t + j * 256;
        out_cb[(size_t)k * CDIM + col] = (cnt > 0) ? v[j] * inv2 : c[j];
    }
}

// ---------------------------------------------------------------------------
// Launch. Inputs: d_in[0] = hidden_states (B*L*C f32), d_in[1] = codebook (K*C f32).
// Output layout: [0, NPTS) cluster ids (as f32), [NPTS, NPTS + K*C) new codebook.
// ---------------------------------------------------------------------------
extern "C" void kernel_launch(void* const* d_in, const int* in_sizes, int n_in,
                              void* d_out, int out_size) {
    const float* hs = (const float*)d_in[0];
    const float* cb = (const float*)d_in[1];
    float* out = (float*)d_out;

    init_kernel<<<512, 256>>>();
    norm_feat_kernel<<<NPTS, 256>>>(hs);
    cbn2_kernel<<<KCB, 256>>>(cb);

    dim3 grid(NPTS / BM, KCB / BKC);  // (64, 32) = 2048 blocks
    argmin_kernel<<<grid, 256>>>(cb);

    scatter_kernel<<<NPTS, 256>>>(out);
    update_kernel<<<KCB, 256>>>(cb, out + NPTS);
}